// round 4
// baseline (speedup 1.0000x reference)
#include <cuda_runtime.h>

// RoiPooling: crop_and_resize(img[0], 2048 boxes, crop=7) over 512 channels.
// Separable bilinear, float2 per thread (256 threads = 512 channels).
// Per image row: 6 independent float2 loads of unique columns x_lo..x_lo+5,
// compile-time BASE_X selects pick sample corners. Rolling 2-row x-interp
// cache in y (CTA-uniform branches). Sized to avoid register spills.

#define IMG_H 28
#define IMG_W 28
#define C2    256          // 512 channels / 2
#define POOLN 7
#define NBOX  2048
#define ROWSTRIDE (IMG_W * C2)   // float2 elems per image row

#define XROW(rowofs, xv) do {                                                 \
    float2 p[6];                                                              \
    _Pragma("unroll")                                                         \
    for (int k = 0; k < 6; k++)                                               \
        p[k] = __ldg(base_img + (rowofs) + colofs[k]);                        \
    _Pragma("unroll")                                                         \
    for (int j = 0; j < POOLN; j++) {                                         \
        const int b = BASE_X[j];                                              \
        float2 c0, c1;                                                        \
        if (cond[j]) { c0 = p[b + 1]; c1 = p[b + 2]; }                        \
        else         { c0 = p[b];     c1 = p[b + 1]; }                        \
        float l = lx[j];                                                      \
        (xv)[j].x = c0.x + (c1.x - c0.x) * l;                                 \
        (xv)[j].y = c0.y + (c1.y - c0.y) * l;                                 \
    }                                                                         \
} while (0)

__global__ __launch_bounds__(256, 3) void roi_pool_kernel(
    const float2* __restrict__ img2,   // img[0] as float2: (28*28, 256)
    const float*  __restrict__ rois,
    float2* __restrict__ out2)
{
    // floor(j * 27*4/(28*6)) for j=0..6; j*sx stays >=0.07 from any integer,
    // far beyond f32 rounding wiggle, so ax[j]-ax[0] ∈ {BASE, BASE+1}.
    const int BASE_X[POOLN] = {0, 0, 1, 1, 2, 3, 3};

    const int box = blockIdx.x;
    const int tid = threadIdx.x;           // channel-pair 0..255

    const float x1 = rois[box * 5 + 3];
    const float y1 = rois[box * 5 + 4];
    const float win = (float)(4.0 / 28.0);
    // Match JAX numerics exactly: ((x1+win)-x1)*27/6 in f32
    const float sx = (((x1 + win) - x1) * 27.0f) / 6.0f;
    const float sy = (((y1 + win) - y1) * 27.0f) / 6.0f;
    const float fx = x1 * 27.0f;
    const float fy = y1 * 27.0f;

    const int x_lo = (int)floorf(fx);      // rois >= 0 so fx >= 0

    float lx[POOLN], mx[POOLN];
    bool cond[POOLN];
#pragma unroll
    for (int j = 0; j < POOLN; j++) {
        float xs = fx + (float)j * sx;
        float xf = floorf(xs);
        lx[j] = xs - xf;
        int ax = (int)xf;
        cond[j] = (ax - x_lo) > BASE_X[j];
        mx[j] = (xs <= 27.0f) ? 1.0f : 0.0f;
    }

    int colofs[6];
#pragma unroll
    for (int k = 0; k < 6; k++)
        colofs[k] = min(x_lo + k, IMG_W - 1) * C2;

    const float2* base_img = img2 + tid;
    float2* outp = out2 + (size_t)box * (POOLN * POOLN) * C2 + tid;

    float2 xvA[POOLN], xvB[POOLN];
    int cy0 = -1000, cy1 = -1000;

#pragma unroll
    for (int i = 0; i < POOLN; i++) {
        float ys = fy + (float)i * sy;
        float yf = floorf(ys);
        float ly = ys - yf;
        int ya = (int)yf;
        int y0 = min(ya, IMG_H - 1);
        int yb = min(ya + 1, IMG_H - 1);
        float my = (ys <= 27.0f) ? 1.0f : 0.0f;

        if (y0 != cy0) {
            if (y0 == cy1) {
#pragma unroll
                for (int j = 0; j < POOLN; j++) xvA[j] = xvB[j];
            } else {
                XROW(y0 * ROWSTRIDE, xvA);
            }
            cy0 = y0;
        }
        if (yb != cy1) {
            if (yb == cy0) {
#pragma unroll
                for (int j = 0; j < POOLN; j++) xvB[j] = xvA[j];
            } else {
                XROW(yb * ROWSTRIDE, xvB);
            }
            cy1 = yb;
        }

        float omly = 1.0f - ly;
#pragma unroll
        for (int j = 0; j < POOLN; j++) {
            float m = my * mx[j];
            float2 v;
            v.x = (xvA[j].x * omly + xvB[j].x * ly) * m;
            v.y = (xvA[j].y * omly + xvB[j].y * ly) * m;
            __stcs(outp + (i * POOLN + j) * C2, v);
        }
    }
}

extern "C" void kernel_launch(void* const* d_in, const int* in_sizes, int n_in,
                              void* d_out, int out_size) {
    const float* img  = (const float*)d_in[0];
    const float* rois = (const float*)d_in[1];
    float* out = (float*)d_out;
    (void)in_sizes; (void)n_in; (void)out_size;
    roi_pool_kernel<<<NBOX, 256>>>((const float2*)img, rois, (float2*)out);
}

// round 5
// speedup vs baseline: 1.3193x; 1.3193x over previous
#include <cuda_runtime.h>

// RoiPooling: crop_and_resize(img[0], 2048 boxes, crop=7) over 512 channels.
// Separable bilinear, float4 per thread (128 threads = 512 channels).
// Per image row: 6 independent float4 loads of unique columns x_lo..x_lo+5,
// compile-time BASE_X + bitmask selects pick sample corners. Rolling 2-row
// x-interp register cache in y (CTA-uniform branches). x-mask folded into the
// cache; reg cap 170 (3 CTAs/SM) so nothing spills.

#define IMG_H 28
#define IMG_W 28
#define C4    128          // 512 channels / 4
#define POOLN 7
#define NBOX  2048
#define ROWSTRIDE (IMG_W * C4)   // float4 elems per image row

// x-interp one image row into xv[0..6], x-mask folded in.
#define XROW(rowofs, xv) do {                                                 \
    float4 p[6];                                                              \
    _Pragma("unroll")                                                         \
    for (int k = 0; k < 6; k++)                                               \
        p[k] = __ldg(base_img + (rowofs) + colofs[k]);                        \
    _Pragma("unroll")                                                         \
    for (int j = 0; j < POOLN; j++) {                                         \
        const int b = BASE_X[j];                                              \
        float4 c0, c1;                                                        \
        if ((condm >> j) & 1) { c0 = p[b + 1]; c1 = p[b + 2]; }               \
        else                  { c0 = p[b];     c1 = p[b + 1]; }               \
        float l = lx[j];                                                      \
        float m = mxf[j];                                                     \
        (xv)[j].x = (c0.x + (c1.x - c0.x) * l) * m;                           \
        (xv)[j].y = (c0.y + (c1.y - c0.y) * l) * m;                           \
        (xv)[j].z = (c0.z + (c1.z - c0.z) * l) * m;                           \
        (xv)[j].w = (c0.w + (c1.w - c0.w) * l) * m;                           \
    }                                                                         \
} while (0)

__global__ __launch_bounds__(128, 3) void roi_pool_kernel(
    const float4* __restrict__ img4,   // img[0] as float4: (28*28, 128)
    const float*  __restrict__ rois,
    float4* __restrict__ out4)
{
    // floor(j * 27*4/(28*6)) for j=0..6; j*sx stays >=0.07 from any integer,
    // far beyond f32 rounding wiggle, so ax[j]-ax[0] ∈ {BASE, BASE+1}.
    const int BASE_X[POOLN] = {0, 0, 1, 1, 2, 3, 3};

    const int box = blockIdx.x;
    const int tid = threadIdx.x;           // channel-quad 0..127

    const float x1 = rois[box * 5 + 3];
    const float y1 = rois[box * 5 + 4];
    const float win = (float)(4.0 / 28.0);
    // Match JAX numerics exactly: ((x1+win)-x1)*27/6 in f32
    const float sx = (((x1 + win) - x1) * 27.0f) / 6.0f;
    const float sy = (((y1 + win) - y1) * 27.0f) / 6.0f;
    const float fx = x1 * 27.0f;
    const float fy = y1 * 27.0f;

    const int x_lo = (int)floorf(fx);      // rois >= 0 so fx >= 0

    float lx[POOLN], mxf[POOLN];
    unsigned condm = 0;
#pragma unroll
    for (int j = 0; j < POOLN; j++) {
        float xs = fx + (float)j * sx;
        float xf = floorf(xs);
        lx[j] = xs - xf;
        int ax = (int)xf;
        if ((ax - x_lo) > BASE_X[j]) condm |= (1u << j);
        mxf[j] = (xs <= 27.0f) ? 1.0f : 0.0f;
    }

    int colofs[6];
#pragma unroll
    for (int k = 0; k < 6; k++)
        colofs[k] = min(x_lo + k, IMG_W - 1) * C4;

    const float4* base_img = img4 + tid;
    float4* outp = out4 + (size_t)box * (POOLN * POOLN) * C4 + tid;

    float4 xvA[POOLN], xvB[POOLN];
    int cy0 = -1000, cy1 = -1000;

#pragma unroll
    for (int i = 0; i < POOLN; i++) {
        float ys = fy + (float)i * sy;
        float yf = floorf(ys);
        float ly = ys - yf;
        int ya = (int)yf;
        int y0 = min(ya, IMG_H - 1);
        int yb = min(ya + 1, IMG_H - 1);
        float my = (ys <= 27.0f) ? 1.0f : 0.0f;

        if (y0 != cy0) {
            if (y0 == cy1) {
#pragma unroll
                for (int j = 0; j < POOLN; j++) xvA[j] = xvB[j];
            } else {
                XROW(y0 * ROWSTRIDE, xvA);
            }
            cy0 = y0;
        }
        if (yb != cy1) {
            if (yb == cy0) {
#pragma unroll
                for (int j = 0; j < POOLN; j++) xvB[j] = xvA[j];
            } else {
                XROW(yb * ROWSTRIDE, xvB);
            }
            cy1 = yb;
        }

        float wA = (1.0f - ly) * my;
        float wB = ly * my;
#pragma unroll
        for (int j = 0; j < POOLN; j++) {
            float4 v;
            v.x = xvA[j].x * wA + xvB[j].x * wB;
            v.y = xvA[j].y * wA + xvB[j].y * wB;
            v.z = xvA[j].z * wA + xvB[j].z * wB;
            v.w = xvA[j].w * wA + xvB[j].w * wB;
            __stcs(outp + (i * POOLN + j) * C4, v);
        }
    }
}

extern "C" void kernel_launch(void* const* d_in, const int* in_sizes, int n_in,
                              void* d_out, int out_size) {
    const float* img  = (const float*)d_in[0];
    const float* rois = (const float*)d_in[1];
    float* out = (float*)d_out;
    (void)in_sizes; (void)n_in; (void)out_size;
    roi_pool_kernel<<<NBOX, 128>>>((const float4*)img, rois, (float4*)out);
}

// round 6
// speedup vs baseline: 1.3522x; 1.0250x over previous
#include <cuda_runtime.h>

// RoiPooling: crop_and_resize(img[0], 2048 boxes, crop=7) over 512 channels.
// Separable bilinear, float4 per thread (128 threads = 512 channels).
// Single-row rolling x-interp register cache: consecutive output rows advance
// the image row by 0 or 1, so caching only the bottom row's x-interp needs
// exactly one fresh 6-load row interpolation per output row. All branches are
// CTA-uniform. Fits under the 128-reg cap (4 CTAs/SM) with no spills.

#define IMG_H 28
#define IMG_W 28
#define C4    128          // 512 channels / 4
#define POOLN 7
#define NBOX  2048
#define ROWSTRIDE (IMG_W * C4)   // float4 elems per image row

// x-interp clamped image row `rowc` into dst[0..6]; x-mask folded into weights.
#define XROWF(rowc, dst) do {                                                 \
    float4 p[6];                                                              \
    const float4* rp = base_img + (rowc) * ROWSTRIDE;                         \
    _Pragma("unroll")                                                         \
    for (int k = 0; k < 6; k++) p[k] = __ldg(rp + colofs[k]);                 \
    _Pragma("unroll")                                                         \
    for (int j = 0; j < POOLN; j++) {                                         \
        const int b = BASE_X[j];                                              \
        float4 c0, c1;                                                        \
        if ((condm >> j) & 1) { c0 = p[b + 1]; c1 = p[b + 2]; }               \
        else                  { c0 = p[b];     c1 = p[b + 1]; }               \
        (dst)[j].x = c0.x * w0[j] + c1.x * w1[j];                             \
        (dst)[j].y = c0.y * w0[j] + c1.y * w1[j];                             \
        (dst)[j].z = c0.z * w0[j] + c1.z * w1[j];                             \
        (dst)[j].w = c0.w * w0[j] + c1.w * w1[j];                             \
    }                                                                         \
} while (0)

// Blend rows T (weight wA) and B (weight wB) and stream-store output row i.
#define STORE_ROW(T, B) do {                                                  \
    _Pragma("unroll")                                                         \
    for (int j = 0; j < POOLN; j++) {                                         \
        float4 v;                                                             \
        v.x = (T)[j].x * wA + (B)[j].x * wB;                                  \
        v.y = (T)[j].y * wA + (B)[j].y * wB;                                  \
        v.z = (T)[j].z * wA + (B)[j].z * wB;                                  \
        v.w = (T)[j].w * wA + (B)[j].w * wB;                                  \
        __stcs(outp + (i * POOLN + j) * C4, v);                               \
    }                                                                         \
} while (0)

__global__ __launch_bounds__(128, 4) void roi_pool_kernel(
    const float4* __restrict__ img4,   // img[0] as float4: (28*28, 128)
    const float*  __restrict__ rois,
    float4* __restrict__ out4)
{
    // floor(j * 27*4/(28*6)) for j=0..6; j*sx stays >=0.07 from any integer,
    // far beyond f32 rounding wiggle, so ax[j]-ax[0] ∈ {BASE, BASE+1}.
    const int BASE_X[POOLN] = {0, 0, 1, 1, 2, 3, 3};

    const int box = blockIdx.x;
    const int tid = threadIdx.x;           // channel-quad 0..127

    const float x1 = rois[box * 5 + 3];
    const float y1 = rois[box * 5 + 4];
    const float win = (float)(4.0 / 28.0);
    // Match JAX numerics: ((x1+win)-x1)*27/6 in f32
    const float sx = (((x1 + win) - x1) * 27.0f) / 6.0f;
    const float sy = (((y1 + win) - y1) * 27.0f) / 6.0f;
    const float fx = x1 * 27.0f;
    const float fy = y1 * 27.0f;

    const int x_lo = (int)floorf(fx);      // rois >= 0 so fx >= 0

    float w0[POOLN], w1[POOLN];
    unsigned condm = 0;
#pragma unroll
    for (int j = 0; j < POOLN; j++) {
        float xs = fx + (float)j * sx;
        float xf = floorf(xs);
        float l = xs - xf;
        int ax = (int)xf;
        if ((ax - x_lo) > BASE_X[j]) condm |= (1u << j);
        float m = (xs <= 27.0f) ? 1.0f : 0.0f;
        w0[j] = m * (1.0f - l);
        w1[j] = m * l;
    }

    int colofs[6];
#pragma unroll
    for (int k = 0; k < 6; k++)
        colofs[k] = min(x_lo + k, IMG_W - 1) * C4;

    const float4* base_img = img4 + tid;
    float4* outp = out4 + (size_t)box * (POOLN * POOLN) * C4 + tid;

    float4 cache[POOLN];                   // x-interp of clamped row `crow`
    int crow = -1000;

#pragma unroll
    for (int i = 0; i < POOLN; i++) {
        float ys = fy + (float)i * sy;
        float yf = floorf(ys);
        float ly = ys - yf;
        int ya = (int)yf;
        int t = min(ya, IMG_H - 1);
        int b = min(ya + 1, IMG_H - 1);
        float my = (ys <= 27.0f) ? 1.0f : 0.0f;
        float wA = (1.0f - ly) * my;
        float wB = ly * my;

        if (t == b) {                      // both clamped to last row
            if (crow != t) { XROWF(t, cache); crow = t; }
            STORE_ROW(cache, cache);
        } else if (crow == t) {            // cache is top; bottom fresh
            float4 fresh[POOLN];
            XROWF(b, fresh);
            STORE_ROW(cache, fresh);
#pragma unroll
            for (int j = 0; j < POOLN; j++) cache[j] = fresh[j];
            crow = b;
        } else if (crow == b) {            // cache is bottom; top fresh
            float4 fresh[POOLN];
            XROWF(t, fresh);
            STORE_ROW(fresh, cache);
        } else {                           // cold start: both fresh
            XROWF(t, cache);
            float4 fresh[POOLN];
            XROWF(b, fresh);
            STORE_ROW(cache, fresh);
#pragma unroll
            for (int j = 0; j < POOLN; j++) cache[j] = fresh[j];
            crow = b;
        }
    }
}

extern "C" void kernel_launch(void* const* d_in, const int* in_sizes, int n_in,
                              void* d_out, int out_size) {
    const float* img  = (const float*)d_in[0];
    const float* rois = (const float*)d_in[1];
    float* out = (float*)d_out;
    (void)in_sizes; (void)n_in; (void)out_size;
    roi_pool_kernel<<<NBOX, 128>>>((const float4*)img, rois, (float4*)out);
}